// round 4
// baseline (speedup 1.0000x reference)
#include <cuda_runtime.h>
#include <cuda_fp16.h>
#include <math.h>

#define NN 100000
#define NE 1000000
#define DIM 64
#define KSTEPS 10
#define FULLMASK 0xffffffffu

// ---------------- static scratch (no allocations allowed) ----------------
__device__ int     g_out_deg[NN];
__device__ int     g_in_deg[NN];
__device__ float   g_src_norm[NN];
__device__ float   g_dst_norm[NN];
__device__ int     g_row_ptr[NN + 1];
__device__ int     g_fill[NN];
__device__ __align__(16)  uint2   g_edge[NE];   // .x = src id, .y = bits(fp32 weight)
__device__ __align__(128) __half2 g_y0[(size_t)NN * (DIM / 2)];
__device__ __align__(128) __half2 g_y1[(size_t)NN * (DIM / 2)];
__device__ __align__(128) __half2 g_fh[(size_t)NN * (DIM / 2)];  // fp16 feat cache
__device__ int     g_blk[256];
__device__ int     g_is64;

__device__ __forceinline__ int edge_at(const int* __restrict__ b, int i, int is64) {
    return b[is64 ? (i << 1) : i];
}

// ---------------- init: zero counters + dtype detect ----------------
__global__ void k_init0(const int* __restrict__ src32, int n) {
    int i = blockIdx.x * blockDim.x + threadIdx.x;
    if (i < n) { g_out_deg[i] = 0; g_in_deg[i] = 0; g_fill[i] = 0; }
    if (i == 0) g_is64 = 1;
    // block 0 probes the first 8KB: int64 data has all-zero odd words
    if (blockIdx.x == 0) {
        for (int j = threadIdx.x; j < 1024; j += blockDim.x)
            if (src32[2 * j + 1] != 0) g_is64 = 0;
    }
}

__global__ void k_count(const int* __restrict__ src,
                        const int* __restrict__ dst, int e) {
    int i = blockIdx.x * blockDim.x + threadIdx.x;
    int is64 = g_is64;
    if (i < e) {
        atomicAdd(&g_out_deg[edge_at(src, i, is64)], 1);
        atomicAdd(&g_in_deg[edge_at(dst, i, is64)], 1);
    }
}

// scan1 also computes both norms (counts are final by now)
__global__ void k_scan1(int n) {
    __shared__ int sh[1024];
    int gid = blockIdx.x * 1024 + threadIdx.x;
    int v = (gid < n) ? g_in_deg[gid] : 0;
    if (gid < n) {
        g_src_norm[gid] = rsqrtf(fmaxf((float)g_out_deg[gid], 1.0f));
        g_dst_norm[gid] = rsqrtf(fmaxf((float)v, 1.0f));
    }
    sh[threadIdx.x] = v;
    __syncthreads();
#pragma unroll
    for (int off = 1; off < 1024; off <<= 1) {
        int t = (threadIdx.x >= (unsigned)off) ? sh[threadIdx.x - off] : 0;
        __syncthreads();
        sh[threadIdx.x] += t;
        __syncthreads();
    }
    if (gid < n) g_row_ptr[gid] = sh[threadIdx.x] - v;   // exclusive
    if (threadIdx.x == 1023) g_blk[blockIdx.x] = sh[1023];
}

__global__ void k_scan2(int nblk, int etotal, int n) {
    if (threadIdx.x == 0 && blockIdx.x == 0) {
        int run = 0;
        for (int b = 0; b < nblk; b++) { int t = g_blk[b]; g_blk[b] = run; run += t; }
        g_row_ptr[n] = etotal;
    }
}

__global__ void k_scan3(int n) {
    int gid = blockIdx.x * 1024 + threadIdx.x;
    if (gid < n) g_row_ptr[gid] += g_blk[blockIdx.x];
}

__global__ void k_fill(const int* __restrict__ src,
                       const int* __restrict__ dst, int e) {
    int i = blockIdx.x * blockDim.x + threadIdx.x;
    int is64 = g_is64;
    if (i < e) {
        int s = edge_at(src, i, is64);
        int d = edge_at(dst, i, is64);
        int pos = g_row_ptr[d] + atomicAdd(&g_fill[d], 1);
        float w = g_src_norm[s] * g_dst_norm[d];
        g_edge[pos] = make_uint2((unsigned)s, __float_as_uint(w));
    }
}

// ---------------- Horner propagation ----------------
// y_K = w_K * feat ; y <- w_k * feat + A_hat * y, k = K-1..0; k=0 writes fp32 out.
__global__ void k_init_y(const float* __restrict__ feat,
                         __half2* __restrict__ y, __half2* __restrict__ fh,
                         float wK, int n32) {
    int i = blockIdx.x * blockDim.x + threadIdx.x;
    if (i < n32) {
        float2 f = *(const float2*)(feat + (size_t)i * 2);
        fh[i] = __floats2half2_rn(f.x, f.y);
        y[i]  = __floats2half2_rn(wK * f.x, wK * f.y);
    }
}

// warp per dst node; lane owns one half2 (2 of 64 cols).
// Edges fetched lane-parallel (one LDG covers up to 32 edges), distributed by shfl.
__global__ void __launch_bounds__(256)
k_step(const __half2* __restrict__ yin, __half2* __restrict__ yout,
       const __half2* __restrict__ fh, const float* __restrict__ feat,
       float* __restrict__ out, float wk, int n, int last) {
    int t = blockIdx.x * blockDim.x + threadIdx.x;
    int node = t >> 5;
    int lane = t & 31;
    if (node >= n) return;
    int base = g_row_ptr[node];
    int deg  = g_row_ptr[node + 1] - base;

    float ax = 0.0f, ay = 0.0f;
    while (deg > 0) {
        int cnt = deg < 32 ? deg : 32;
        uint2 ed = make_uint2(0u, 0u);
        if (lane < cnt) ed = g_edge[base + lane];

        int j = 0;
        for (; j + 4 <= cnt; j += 4) {
            int   s0 = __shfl_sync(FULLMASK, ed.x, j);
            int   s1 = __shfl_sync(FULLMASK, ed.x, j + 1);
            int   s2 = __shfl_sync(FULLMASK, ed.x, j + 2);
            int   s3 = __shfl_sync(FULLMASK, ed.x, j + 3);
            float w0 = __uint_as_float(__shfl_sync(FULLMASK, ed.y, j));
            float w1 = __uint_as_float(__shfl_sync(FULLMASK, ed.y, j + 1));
            float w2 = __uint_as_float(__shfl_sync(FULLMASK, ed.y, j + 2));
            float w3 = __uint_as_float(__shfl_sync(FULLMASK, ed.y, j + 3));
            float2 v0 = __half22float2(yin[(size_t)s0 * 32 + lane]);
            float2 v1 = __half22float2(yin[(size_t)s1 * 32 + lane]);
            float2 v2 = __half22float2(yin[(size_t)s2 * 32 + lane]);
            float2 v3 = __half22float2(yin[(size_t)s3 * 32 + lane]);
            ax += w0 * v0.x; ay += w0 * v0.y;
            ax += w1 * v1.x; ay += w1 * v1.y;
            ax += w2 * v2.x; ay += w2 * v2.y;
            ax += w3 * v3.x; ay += w3 * v3.y;
        }
        for (; j < cnt; j++) {
            int   s = __shfl_sync(FULLMASK, ed.x, j);
            float w = __uint_as_float(__shfl_sync(FULLMASK, ed.y, j));
            float2 v = __half22float2(yin[(size_t)s * 32 + lane]);
            ax += w * v.x; ay += w * v.y;
        }
        base += cnt; deg -= cnt;
    }

    if (last) {
        // fp32 feat for the final direct-feat term
        float2 f = *(const float2*)(feat + (size_t)node * DIM + lane * 2);
        *(float2*)(out + (size_t)node * DIM + lane * 2) =
            make_float2(fmaf(wk, f.x, ax), fmaf(wk, f.y, ay));
    } else {
        float2 f = __half22float2(fh[(size_t)node * 32 + lane]);
        yout[(size_t)node * 32 + lane] =
            __floats2half2_rn(fmaf(wk, f.x, ax), fmaf(wk, f.y, ay));
    }
}

// ---------------- launch ----------------
extern "C" void kernel_launch(void* const* d_in, const int* in_sizes, int n_in,
                              void* d_out, int out_size) {
    const float* feat  = (const float*)d_in[0];
    const int*   src32 = (const int*)d_in[1];
    const int*   dst32 = (const int*)d_in[2];
    float* out = (float*)d_out;

    int n = in_sizes[0] / DIM;   // 100000
    int e = in_sizes[1];         // 1000000

    void *p0, *p1, *p2;
    cudaGetSymbolAddress(&p0, g_y0);
    cudaGetSymbolAddress(&p1, g_y1);
    cudaGetSymbolAddress(&p2, g_fh);
    __half2* y0 = (__half2*)p0;
    __half2* y1 = (__half2*)p1;
    __half2* fh = (__half2*)p2;

    // log weights: w[j] = log(BETA + 1 + j)/denom, BETA = 2
    double logs[KSTEPS + 1]; double denom = 0.0;
    for (int j = 0; j <= KSTEPS; j++) { logs[j] = log(3.0 + (double)j); denom += logs[j]; }

    int nb_n = (n + 255) / 256;
    int nb_e = (e + 255) / 256;
    int nblk = (n + 1023) / 1024;

    k_init0<<<nb_n, 256>>>(src32, n);
    k_count<<<nb_e, 256>>>(src32, dst32, e);
    k_scan1<<<nblk, 1024>>>(n);
    k_scan2<<<1, 32>>>(nblk, e, n);
    k_scan3<<<nblk, 1024>>>(n);
    k_fill <<<nb_e, 256>>>(src32, dst32, e);

    int n32 = n * 32;
    k_init_y<<<(n32 + 255) / 256, 256>>>(feat, y0, fh, (float)(logs[KSTEPS] / denom), n32);

    int nb_s = (n32 + 255) / 256;
    __half2* yin = y0;
    __half2* yout = y1;
    for (int k = KSTEPS - 1; k >= 0; k--) {
        k_step<<<nb_s, 256>>>(yin, yout, fh, feat, out,
                              (float)(logs[k] / denom), n, k == 0);
        __half2* tmp = yin; yin = yout; yout = tmp;
    }
}